// round 1
// baseline (speedup 1.0000x reference)
#include <cuda_runtime.h>
#include <math.h>

// Problem constants (shapes fixed by the dataset)
#define NMAX 100000
#define HT 16   // hull edges per tile

// ---------------- scratch (static device globals; no allocation) ----------------
__device__ float g_v   [(size_t)NMAX * 128];
__device__ float g_vhull[(size_t)NMAX * 128];
__device__ float g_oh  [(size_t)NMAX * 128];
__device__ float g_t128[(size_t)NMAX * 128];
__device__ float g_a256[(size_t)NMAX * 256];
__device__ float g_b256[(size_t)NMAX * 256];

__device__ __forceinline__ float silu_f(float x) { return x / (1.0f + expf(-x)); }

// ---------------- zero two [N,128] buffers ----------------
__global__ void zero_kernel(float* a, float* b, size_t n)
{
    size_t t = (size_t)blockIdx.x * blockDim.x + threadIdx.x;
    size_t stride = (size_t)gridDim.x * blockDim.x;
    for (size_t x = t; x < n; x += stride) { a[x] = 0.0f; b[x] = 0.0f; }
}

// ---------------- scatter: v = segment_sum(e2, i) ----------------
// one thread handles one (edge, 4-col group); float4 load, 4 atomics
__global__ void scatter_kernel(const float4* __restrict__ e2,
                               const int* __restrict__ idx,
                               float* __restrict__ v, int E)
{
    int t = blockIdx.x * blockDim.x + threadIdx.x;
    int e = t >> 5;
    int c = t & 31;
    if (e >= E) return;
    float4 val = e2[(size_t)e * 32 + c];
    int node = idx[e];
    float* dst = v + (size_t)node * 128 + c * 4;
    atomicAdd(dst + 0, val.x);
    atomicAdd(dst + 1, val.y);
    atomicAdd(dst + 2, val.z);
    atomicAdd(dst + 3, val.w);
}

// ---------------- generic tiled fp32 GEMM with fused concat/bias/silu ----------
// C[N,M] = act( [A0 | A1][N,K] @ W[K,M] + bias )
// A columns [0,ksplit) from A0 (leading dim lda0), [ksplit,K) from A1 (lda1).
#define BM 64
#define BN 64
#define BK 16

__global__ __launch_bounds__(256) void gemm_kernel(
    const float* __restrict__ A0, int lda0, int ksplit,
    const float* __restrict__ A1, int lda1,
    const float* __restrict__ W, const float* __restrict__ bias,
    float* __restrict__ C, int Nrows, int K, int M, int act)
{
    __shared__ float As[BM][BK + 1];
    __shared__ float Bs[BK][BN];

    int row0 = blockIdx.x * BM;
    int col0 = blockIdx.y * BN;
    int tid = threadIdx.x;
    int tr = tid >> 4;          // 0..15
    int tc = tid & 15;          // 0..15

    float acc[4][4];
#pragma unroll
    for (int x = 0; x < 4; x++)
#pragma unroll
        for (int y = 0; y < 4; y++) acc[x][y] = 0.0f;

    for (int k0 = 0; k0 < K; k0 += BK) {
        // A tile: BM x BK
#pragma unroll
        for (int t = tid; t < BM * BK; t += 256) {
            int r = t >> 4;        // /BK
            int kk = t & 15;       // %BK
            int grow = row0 + r;
            int gk = k0 + kk;
            float v = 0.0f;
            if (grow < Nrows) {
                v = (gk < ksplit) ? A0[(size_t)grow * lda0 + gk]
                                  : A1[(size_t)grow * lda1 + (gk - ksplit)];
            }
            As[r][kk] = v;
        }
        // B tile: BK x BN (W stored [K, M] row-major -> coalesced in m)
#pragma unroll
        for (int t = tid; t < BK * BN; t += 256) {
            int kk = t >> 6;       // /BN
            int m  = t & 63;       // %BN
            int gm = col0 + m;
            Bs[kk][m] = (gm < M) ? W[(size_t)(k0 + kk) * M + gm] : 0.0f;
        }
        __syncthreads();

#pragma unroll
        for (int kk = 0; kk < BK; kk++) {
            float a[4], b[4];
#pragma unroll
            for (int x = 0; x < 4; x++) a[x] = As[tr * 4 + x][kk];
#pragma unroll
            for (int y = 0; y < 4; y++) b[y] = Bs[kk][tc * 4 + y];
#pragma unroll
            for (int x = 0; x < 4; x++)
#pragma unroll
                for (int y = 0; y < 4; y++) acc[x][y] += a[x] * b[y];
        }
        __syncthreads();
    }

#pragma unroll
    for (int x = 0; x < 4; x++) {
        int grow = row0 + tr * 4 + x;
        if (grow >= Nrows) break;
#pragma unroll
        for (int y = 0; y < 4; y++) {
            int gm = col0 + tc * 4 + y;
            if (gm >= M) continue;
            float v = acc[x][y];
            if (bias) v += bias[gm];
            if (act)  v = silu_f(v);
            C[(size_t)grow * M + gm] = v;
        }
    }
}

// ---------------- fused hull edge kernel ----------------
// per hull edge e: h = silu(fea[e] @ w0 + b0); Wh = h @ w1 + b1;
//                  oh[i_[e]] += v_hull[j_[e]] * Wh    (atomic)
// Dynamic smem layout (floats): w1[16384] w0[2048] b0[128] b1[128] fea[HT*16] hid[HT*128]
#define HULL_SMEM_FLOATS (16384 + 2048 + 128 + 128 + HT*16 + HT*128)

__global__ __launch_bounds__(128) void hull_kernel(
    const float* __restrict__ fea,
    const int* __restrict__ jidx, const int* __restrict__ iidx,
    const float* __restrict__ w0, const float* __restrict__ b0,
    const float* __restrict__ w1, const float* __restrict__ b1,
    const float* __restrict__ vhull, float* __restrict__ oh, int EHn)
{
    extern __shared__ float sm[];
    float* s_w1  = sm;                       // 128*128
    float* s_w0  = s_w1 + 16384;             // 16*128
    float* s_b0  = s_w0 + 2048;
    float* s_b1  = s_b0 + 128;
    float* s_fea = s_b1 + 128;               // HT*16
    float* s_hid = s_fea + HT * 16;          // HT*128

    int tid = threadIdx.x;
    for (int t = tid; t < 16384; t += 128) s_w1[t] = w1[t];
    for (int t = tid; t < 2048;  t += 128) s_w0[t] = w0[t];
    s_b0[tid] = b0[tid];
    s_b1[tid] = b1[tid];
    __syncthreads();

    for (int base = blockIdx.x * HT; base < EHn; base += gridDim.x * HT) {
        int ec = min(HT, EHn - base);

        for (int t = tid; t < ec * 16; t += 128)
            s_fea[t] = fea[(size_t)base * 16 + t];
        __syncthreads();

        // hidden = silu(fea @ w0 + b0)  : thread owns column `tid`
        for (int e = 0; e < ec; e++) {
            float acc = s_b0[tid];
#pragma unroll
            for (int k = 0; k < 16; k++)
                acc += s_fea[e * 16 + k] * s_w0[k * 128 + tid];
            s_hid[e * 128 + tid] = silu_f(acc);
        }
        __syncthreads();

        // Wh = hid @ w1 + b1; multiply by gathered v_hull; atomic scatter
        for (int eo = 0; eo < ec; eo += 4) {
            int ne = min(4, ec - eo);
            float acc[4];
            int jj[4], ii[4];
            for (int e = 0; e < ne; e++) {
                acc[e] = s_b1[tid];
                jj[e] = jidx[base + eo + e];
                ii[e] = iidx[base + eo + e];
            }
            if (ne == 4) {
#pragma unroll 8
                for (int k = 0; k < 128; k += 4) {
                    float wv0 = s_w1[(k + 0) * 128 + tid];
                    float wv1 = s_w1[(k + 1) * 128 + tid];
                    float wv2 = s_w1[(k + 2) * 128 + tid];
                    float wv3 = s_w1[(k + 3) * 128 + tid];
#pragma unroll
                    for (int e = 0; e < 4; e++) {
                        float4 h = *(const float4*)&s_hid[(eo + e) * 128 + k];
                        acc[e] += h.x * wv0 + h.y * wv1 + h.z * wv2 + h.w * wv3;
                    }
                }
            } else {
                for (int k = 0; k < 128; k++) {
                    float wv = s_w1[k * 128 + tid];
                    for (int e = 0; e < ne; e++)
                        acc[e] += s_hid[(eo + e) * 128 + k] * wv;
                }
            }
            for (int e = 0; e < ne; e++) {
                float ev = vhull[(size_t)jj[e] * 128 + tid] * acc[e];
                atomicAdd(&oh[(size_t)ii[e] * 128 + tid], ev);
            }
        }
        __syncthreads();
    }
}

// ---------------- final dot: out[n] = A[n,:256] . w_out ----------------
__global__ void out_kernel(const float* __restrict__ A,
                           const float* __restrict__ w,
                           float* __restrict__ out, int Nrows)
{
    int gwarp = (blockIdx.x * blockDim.x + threadIdx.x) >> 5;
    int lane = threadIdx.x & 31;
    if (gwarp >= Nrows) return;
    const float* row = A + (size_t)gwarp * 256;
    float acc = 0.0f;
#pragma unroll
    for (int k = lane; k < 256; k += 32) acc += row[k] * __ldg(&w[k]);
#pragma unroll
    for (int o = 16; o > 0; o >>= 1)
        acc += __shfl_down_sync(0xffffffff, acc, o);
    if (lane == 0) out[gwarp] = acc;
}

// ---------------- launch ----------------
extern "C" void kernel_launch(void* const* d_in, const int* in_sizes, int n_in,
                              void* d_out, int out_size)
{
    const float* e2    = (const float*)d_in[0];
    const int*   iedge = (const int*)  d_in[1];
    const float* fea   = (const float*)d_in[2];
    const int*   eih   = (const int*)  d_in[3];
    const float* w_hull= (const float*)d_in[4];
    const float* w0    = (const float*)d_in[5];
    const float* b0    = (const float*)d_in[6];
    const float* w1    = (const float*)d_in[7];
    const float* b1    = (const float*)d_in[8];
    const float* w1h   = (const float*)d_in[9];
    const float* b1h   = (const float*)d_in[10];
    const float* w2h   = (const float*)d_in[11];
    const float* b2h   = (const float*)d_in[12];
    const float* wcat  = (const float*)d_in[13];
    const float* bcat  = (const float*)d_in[14];
    const float* wup   = (const float*)d_in[15];
    const float* bup   = (const float*)d_in[16];
    const float* wl0   = (const float*)d_in[17];
    const float* bl0   = (const float*)d_in[18];
    const float* wl1   = (const float*)d_in[19];
    const float* bl1   = (const float*)d_in[20];
    const float* wout  = (const float*)d_in[21];
    float* out = (float*)d_out;

    int N  = out_size;              // OC = 1
    int E  = in_sizes[1];           // count of edge index i
    int EH = in_sizes[2] / 16;      // fea_hull rows
    const int* jh = eih;            // edge_index_hull[0]
    const int* ih = eih + EH;       // edge_index_hull[1]

    float *pv, *pvh, *poh, *pt, *pa, *pb;
    cudaGetSymbolAddress((void**)&pv,  g_v);
    cudaGetSymbolAddress((void**)&pvh, g_vhull);
    cudaGetSymbolAddress((void**)&poh, g_oh);
    cudaGetSymbolAddress((void**)&pt,  g_t128);
    cudaGetSymbolAddress((void**)&pa,  g_a256);
    cudaGetSymbolAddress((void**)&pb,  g_b256);

    // 1. zero accumulators
    zero_kernel<<<2048, 256>>>(pv, poh, (size_t)N * 128);

    // 2. v = segment_sum(e2, i)
    {
        long long threads = (long long)E * 32;
        int blocks = (int)((threads + 255) / 256);
        scatter_kernel<<<blocks, 256>>>((const float4*)e2, iedge, pv, E);
    }

    int rowBlocks = (N + BM - 1) / BM;

    // 3. v_hull = v @ w_hull
    gemm_kernel<<<dim3(rowBlocks, 2), 256>>>(pv, 128, 128, pv, 128,
                                             w_hull, nullptr, pvh, N, 128, 128, 0);

    // 4. hull message passing (fused MLP + gather*mul + atomic scatter)
    {
        size_t smem = HULL_SMEM_FLOATS * sizeof(float);
        cudaFuncSetAttribute(hull_kernel,
                             cudaFuncAttributeMaxDynamicSharedMemorySize, (int)smem);
        hull_kernel<<<1184, 128, smem>>>(fea, jh, ih, w0, b0, w1, b1, pvh, poh, EH);
    }

    // 5. t128 = silu(oh @ w1_hull + b1_hull)
    gemm_kernel<<<dim3(rowBlocks, 2), 256>>>(poh, 128, 128, poh, 128,
                                             w1h, b1h, pt, N, 128, 128, 1);
    // 6. a256 = t128 @ w2_hull + b2_hull
    gemm_kernel<<<dim3(rowBlocks, 4), 256>>>(pt, 128, 128, pt, 128,
                                             w2h, b2h, pa, N, 128, 256, 0);
    // 7. t128 = silu([v | a256] @ w_cat + b_cat)    (K = 384 concat)
    gemm_kernel<<<dim3(rowBlocks, 2), 256>>>(pv, 128, 128, pa, 256,
                                             wcat, bcat, pt, N, 384, 128, 1);
    // 8. b256 = t128 @ w_up + b_up
    gemm_kernel<<<dim3(rowBlocks, 4), 256>>>(pt, 128, 128, pt, 128,
                                             wup, bup, pb, N, 128, 256, 0);
    // 9. a256 = silu(b256 @ w_l0 + b_l0)
    gemm_kernel<<<dim3(rowBlocks, 4), 256>>>(pb, 256, 256, pb, 256,
                                             wl0, bl0, pa, N, 256, 256, 1);
    // 10. b256 = silu(a256 @ w_l1 + b_l1)
    gemm_kernel<<<dim3(rowBlocks, 4), 256>>>(pa, 256, 256, pa, 256,
                                             wl1, bl1, pb, N, 256, 256, 1);
    // 11. out = b256 @ w_out
    {
        int warpsPerBlock = 8;
        int blocks = (N + warpsPerBlock - 1) / warpsPerBlock;
        out_kernel<<<blocks, 256>>>(pb, wout, out, N);
    }
}

// round 3
// speedup vs baseline: 2.1936x; 2.1936x over previous
#include <cuda_runtime.h>
#include <cuda_bf16.h>
#include <math.h>
#include <stdint.h>

#define NMAX 100000
#define KBLK 32      // K elements per SMEM tile block
#define HTILE 32     // hull edges per tile
#define SAS 40       // sA stride in bf16 (conflict-free frag loads)
#define SBS 42       // sB stride in bf16 (conflict-free frag loads)

// ---------------- scratch ----------------
__device__ float g_v   [(size_t)NMAX * 128];
__device__ float g_vhull[(size_t)NMAX * 128];
__device__ float g_oh  [(size_t)NMAX * 128];
__device__ float g_t128[(size_t)NMAX * 128];
__device__ float g_a256[(size_t)NMAX * 256];
__device__ float g_b256[(size_t)NMAX * 256];

__device__ __forceinline__ float silu_f(float x) { return x / (1.0f + expf(-x)); }

__device__ __forceinline__ void mma_bf16(float* c, uint32_t a0, uint32_t a1,
                                         uint32_t a2, uint32_t a3,
                                         uint32_t b0, uint32_t b1) {
    asm volatile(
        "mma.sync.aligned.m16n8k16.row.col.f32.bf16.bf16.f32 "
        "{%0,%1,%2,%3}, {%4,%5,%6,%7}, {%8,%9}, {%0,%1,%2,%3};"
        : "+f"(c[0]), "+f"(c[1]), "+f"(c[2]), "+f"(c[3])
        : "r"(a0), "r"(a1), "r"(a2), "r"(a3), "r"(b0), "r"(b1));
}

__device__ __forceinline__ uint32_t packbf(__nv_bfloat16 lo, __nv_bfloat16 hi) {
    return (uint32_t)__bfloat16_as_ushort(lo) | ((uint32_t)__bfloat16_as_ushort(hi) << 16);
}

// ---------------- simple kernels ----------------
__global__ void zero_kernel(float* a, float* b, size_t n)
{
    size_t t = (size_t)blockIdx.x * blockDim.x + threadIdx.x;
    size_t stride = (size_t)gridDim.x * blockDim.x;
    for (size_t x = t; x < n; x += stride) { a[x] = 0.0f; b[x] = 0.0f; }
}

__global__ void scatter_kernel(const float4* __restrict__ e2,
                               const int* __restrict__ idx,
                               float* __restrict__ v, int E)
{
    int t = blockIdx.x * blockDim.x + threadIdx.x;
    int e = t >> 5;
    int c = t & 31;
    if (e >= E) return;
    float4 val = e2[(size_t)e * 32 + c];
    int node = idx[e];
    float* dst = v + (size_t)node * 128 + c * 4;
    atomicAdd(dst + 0, val.x);
    atomicAdd(dst + 1, val.y);
    atomicAdd(dst + 2, val.z);
    atomicAdd(dst + 3, val.w);
}

__global__ void out_kernel(const float* __restrict__ A,
                           const float* __restrict__ w,
                           float* __restrict__ out, int Nrows)
{
    int gwarp = (blockIdx.x * blockDim.x + threadIdx.x) >> 5;
    int lane = threadIdx.x & 31;
    if (gwarp >= Nrows) return;
    const float* row = A + (size_t)gwarp * 256;
    float acc = 0.0f;
#pragma unroll
    for (int k = lane; k < 256; k += 32) acc += row[k] * __ldg(&w[k]);
#pragma unroll
    for (int o = 16; o > 0; o >>= 1) acc += __shfl_down_sync(0xffffffff, acc, o);
    if (lane == 0) out[gwarp] = acc;
}

// ---------------- warp-MMA bf16 split-3 GEMM ----------------
// C[Nrows, M] = act( [A0|A1] @ W + bias ), W row-major [K, M].
// CTA: 128 rows x 128 cols; grid.y = M/128. K, ksplit multiples of 32.
// Each fp32 value x = hi(bf16) + lo(bf16); acc += Ahi*Bhi + Ahi*Blo + Alo*Bhi.
__global__ __launch_bounds__(256, 2) void gemm_mma(
    const float* __restrict__ A0, int lda0, int ksplit,
    const float* __restrict__ A1, int lda1,
    const float* __restrict__ W, const float* __restrict__ bias,
    float* __restrict__ C, int Nrows, int K, int M, int act)
{
    __shared__ __nv_bfloat16 sAhi[128 * SAS];
    __shared__ __nv_bfloat16 sAlo[128 * SAS];
    __shared__ __nv_bfloat16 sBhi[128 * SBS];
    __shared__ __nv_bfloat16 sBlo[128 * SBS];

    int tid = threadIdx.x;
    int wid = tid >> 5;
    int lane = tid & 31;
    int warpRow = wid & 3;       // 4 row-warps x 32 rows
    int warpCol = wid >> 2;      // 2 col-warps x 64 cols
    int row0 = blockIdx.x * 128;
    int col0 = blockIdx.y * 128;

    float c[2][8][4];
#pragma unroll
    for (int mf = 0; mf < 2; mf++)
#pragma unroll
        for (int nf = 0; nf < 8; nf++)
#pragma unroll
            for (int q = 0; q < 4; q++) c[mf][nf][q] = 0.0f;

    int qrow = lane >> 2;        // 0..7
    int qcol = lane & 3;         // 0..3

    for (int k0 = 0; k0 < K; k0 += KBLK) {
        // ---- load + convert A tile (128 x 32 fp32 -> bf16 hi/lo) ----
        const float* srcA;
        int kbase, ld;
        if (k0 < ksplit) { srcA = A0; kbase = k0; ld = lda0; }
        else             { srcA = A1; kbase = k0 - ksplit; ld = lda1; }
#pragma unroll
        for (int it = 0; it < 4; it++) {
            int idx = tid + it * 256;          // 1024 float4
            int r = idx >> 3;
            int kq = (idx & 7) * 4;
            float4 v = make_float4(0.f, 0.f, 0.f, 0.f);
            int grow = row0 + r;
            if (grow < Nrows)
                v = *(const float4*)&srcA[(size_t)grow * ld + kbase + kq];
            __nv_bfloat16 h0 = __float2bfloat16(v.x), h1 = __float2bfloat16(v.y);
            __nv_bfloat16 h2 = __float2bfloat16(v.z), h3 = __float2bfloat16(v.w);
            __nv_bfloat16 l0 = __float2bfloat16(v.x - __bfloat162float(h0));
            __nv_bfloat16 l1 = __float2bfloat16(v.y - __bfloat162float(h1));
            __nv_bfloat16 l2 = __float2bfloat16(v.z - __bfloat162float(h2));
            __nv_bfloat16 l3 = __float2bfloat16(v.w - __bfloat162float(h3));
            int base = r * SAS + kq;
            *(uint32_t*)&sAhi[base]     = packbf(h0, h1);
            *(uint32_t*)&sAhi[base + 2] = packbf(h2, h3);
            *(uint32_t*)&sAlo[base]     = packbf(l0, l1);
            *(uint32_t*)&sAlo[base + 2] = packbf(l2, l3);
        }
        // ---- load + convert B tile: rows k0..k0+31 of W, cols col0..col0+127 ----
#pragma unroll
        for (int it = 0; it < 4; it++) {
            int idx = tid + it * 256;          // 1024 float4
            int k = idx >> 5;                  // 0..31
            int nq = (idx & 31) * 4;           // 0..124
            float4 v = *(const float4*)&W[(size_t)(k0 + k) * M + col0 + nq];
            __nv_bfloat16 h0 = __float2bfloat16(v.x), h1 = __float2bfloat16(v.y);
            __nv_bfloat16 h2 = __float2bfloat16(v.z), h3 = __float2bfloat16(v.w);
            __nv_bfloat16 l0 = __float2bfloat16(v.x - __bfloat162float(h0));
            __nv_bfloat16 l1 = __float2bfloat16(v.y - __bfloat162float(h1));
            __nv_bfloat16 l2 = __float2bfloat16(v.z - __bfloat162float(h2));
            __nv_bfloat16 l3 = __float2bfloat16(v.w - __bfloat162float(h3));
            sBhi[(nq + 0) * SBS + k] = h0;  sBlo[(nq + 0) * SBS + k] = l0;
            sBhi[(nq + 1) * SBS + k] = h1;  sBlo[(nq + 1) * SBS + k] = l1;
            sBhi[(nq + 2) * SBS + k] = h2;  sBlo[(nq + 2) * SBS + k] = l2;
            sBhi[(nq + 3) * SBS + k] = h3;  sBlo[(nq + 3) * SBS + k] = l3;
        }
        __syncthreads();

        // ---- compute: 2 k16-chunks ----
#pragma unroll
        for (int kc = 0; kc < KBLK; kc += 16) {
            uint32_t ah[2][4], al[2][4];
#pragma unroll
            for (int mf = 0; mf < 2; mf++) {
                int r = warpRow * 32 + mf * 16 + qrow;
                int i0 = r * SAS + kc + 2 * qcol;
                ah[mf][0] = *(const uint32_t*)&sAhi[i0];
                ah[mf][1] = *(const uint32_t*)&sAhi[i0 + 8 * SAS];
                ah[mf][2] = *(const uint32_t*)&sAhi[i0 + 8];
                ah[mf][3] = *(const uint32_t*)&sAhi[i0 + 8 * SAS + 8];
                al[mf][0] = *(const uint32_t*)&sAlo[i0];
                al[mf][1] = *(const uint32_t*)&sAlo[i0 + 8 * SAS];
                al[mf][2] = *(const uint32_t*)&sAlo[i0 + 8];
                al[mf][3] = *(const uint32_t*)&sAlo[i0 + 8 * SAS + 8];
            }
#pragma unroll
            for (int nf = 0; nf < 8; nf++) {
                int n = warpCol * 64 + nf * 8 + qrow;
                int i0 = n * SBS + kc + 2 * qcol;
                uint32_t bh0 = *(const uint32_t*)&sBhi[i0];
                uint32_t bh1 = *(const uint32_t*)&sBhi[i0 + 8];
                uint32_t bl0 = *(const uint32_t*)&sBlo[i0];
                uint32_t bl1 = *(const uint32_t*)&sBlo[i0 + 8];
#pragma unroll
                for (int mf = 0; mf < 2; mf++) {
                    mma_bf16(c[mf][nf], ah[mf][0], ah[mf][1], ah[mf][2], ah[mf][3], bh0, bh1);
                    mma_bf16(c[mf][nf], ah[mf][0], ah[mf][1], ah[mf][2], ah[mf][3], bl0, bl1);
                    mma_bf16(c[mf][nf], al[mf][0], al[mf][1], al[mf][2], al[mf][3], bh0, bh1);
                }
            }
        }
        __syncthreads();
    }

    // ---- epilogue: bias + silu + store ----
#pragma unroll
    for (int mf = 0; mf < 2; mf++) {
        int rbase = row0 + warpRow * 32 + mf * 16 + qrow;
#pragma unroll
        for (int nf = 0; nf < 8; nf++) {
            int colp = col0 + warpCol * 64 + nf * 8 + 2 * qcol;
            float b0v = 0.f, b1v = 0.f;
            if (bias) { b0v = bias[colp]; b1v = bias[colp + 1]; }
            float f0 = c[mf][nf][0] + b0v;
            float f1 = c[mf][nf][1] + b1v;
            float f2 = c[mf][nf][2] + b0v;
            float f3 = c[mf][nf][3] + b1v;
            if (act) { f0 = silu_f(f0); f1 = silu_f(f1); f2 = silu_f(f2); f3 = silu_f(f3); }
            if (rbase < Nrows)
                *(float2*)&C[(size_t)rbase * M + colp] = make_float2(f0, f1);
            if (rbase + 8 < Nrows)
                *(float2*)&C[(size_t)(rbase + 8) * M + colp] = make_float2(f2, f3);
        }
    }
}

// ---------------- fused hull edge kernel (256 threads, 32-edge tiles) --------
#define HULL_SMEM_FLOATS (16384 + HTILE * 16 + HTILE * 128)

__global__ __launch_bounds__(256) void hull_kernel(
    const float* __restrict__ fea,
    const int* __restrict__ jidx, const int* __restrict__ iidx,
    const float* __restrict__ w0, const float* __restrict__ b0,
    const float* __restrict__ w1, const float* __restrict__ b1,
    const float* __restrict__ vhull, float* __restrict__ oh, int EHn)
{
    extern __shared__ float sm[];
    float* s_w1  = sm;                       // 128*128
    float* s_fea = s_w1 + 16384;             // HTILE*16
    float* s_hid = s_fea + HTILE * 16;       // HTILE*128

    int tid = threadIdx.x;
    int col = tid & 127;
    int wg  = tid >> 7;                      // 0 or 1

    for (int t = tid; t < 16384; t += 256) s_w1[t] = w1[t];
    float rw0[16];
#pragma unroll
    for (int k = 0; k < 16; k++) rw0[k] = w0[k * 128 + col];
    float rb0 = b0[col];
    float rb1 = b1[col];
    __syncthreads();

    for (int base = blockIdx.x * HTILE; base < EHn; base += gridDim.x * HTILE) {
        int ec = min(HTILE, EHn - base);

        for (int t = tid; t < ec * 16; t += 256)
            s_fea[t] = fea[(size_t)base * 16 + t];
        __syncthreads();

        int e0 = wg * 16, e1 = min(ec, e0 + 16);
        for (int e = e0; e < e1; e++) {
            float acc = rb0;
#pragma unroll
            for (int k = 0; k < 16; k++)
                acc += s_fea[e * 16 + k] * rw0[k];
            s_hid[e * 128 + col] = silu_f(acc);
        }
        __syncthreads();

        for (int eo = e0; eo < e1; eo += 4) {
            int ne = min(4, e1 - eo);
            float acc[4];
            int jj[4], ii[4];
            for (int e = 0; e < ne; e++) {
                acc[e] = rb1;
                jj[e] = jidx[base + eo + e];
                ii[e] = iidx[base + eo + e];
            }
            if (ne == 4) {
#pragma unroll 8
                for (int k = 0; k < 128; k += 4) {
                    float wv0 = s_w1[(k + 0) * 128 + col];
                    float wv1 = s_w1[(k + 1) * 128 + col];
                    float wv2 = s_w1[(k + 2) * 128 + col];
                    float wv3 = s_w1[(k + 3) * 128 + col];
#pragma unroll
                    for (int e = 0; e < 4; e++) {
                        float4 h = *(const float4*)&s_hid[(eo + e) * 128 + k];
                        acc[e] += h.x * wv0 + h.y * wv1 + h.z * wv2 + h.w * wv3;
                    }
                }
            } else {
                for (int k = 0; k < 128; k++) {
                    float wv = s_w1[k * 128 + col];
                    for (int e = 0; e < ne; e++)
                        acc[e] += s_hid[(eo + e) * 128 + k] * wv;
                }
            }
            for (int e = 0; e < ne; e++) {
                float ev = vhull[(size_t)jj[e] * 128 + col] * acc[e];
                atomicAdd(&oh[(size_t)ii[e] * 128 + col], ev);
            }
        }
        __syncthreads();
    }
}

// ---------------- launch ----------------
static void launch_gemm(const float* A0, int lda0, int ksplit,
                        const float* A1, int lda1,
                        const float* W, const float* bias,
                        float* C, int N, int K, int M, int act)
{
    dim3 grid((N + 127) / 128, M / 128);
    gemm_mma<<<grid, 256>>>(A0, lda0, ksplit, A1, lda1, W, bias, C, N, K, M, act);
}

extern "C" void kernel_launch(void* const* d_in, const int* in_sizes, int n_in,
                              void* d_out, int out_size)
{
    const float* e2    = (const float*)d_in[0];
    const int*   iedge = (const int*)  d_in[1];
    const float* fea   = (const float*)d_in[2];
    const int*   eih   = (const int*)  d_in[3];
    const float* w_hull= (const float*)d_in[4];
    const float* w0    = (const float*)d_in[5];
    const float* b0    = (const float*)d_in[6];
    const float* w1    = (const float*)d_in[7];
    const float* b1    = (const float*)d_in[8];
    const float* w1h   = (const float*)d_in[9];
    const float* b1h   = (const float*)d_in[10];
    const float* w2h   = (const float*)d_in[11];
    const float* b2h   = (const float*)d_in[12];
    const float* wcat  = (const float*)d_in[13];
    const float* bcat  = (const float*)d_in[14];
    const float* wup   = (const float*)d_in[15];
    const float* bup   = (const float*)d_in[16];
    const float* wl0   = (const float*)d_in[17];
    const float* bl0   = (const float*)d_in[18];
    const float* wl1   = (const float*)d_in[19];
    const float* bl1   = (const float*)d_in[20];
    const float* wout  = (const float*)d_in[21];
    float* out = (float*)d_out;

    int N  = out_size;
    int E  = in_sizes[1];
    int EH = in_sizes[2] / 16;
    const int* jh = eih;
    const int* ih = eih + EH;

    float *pv, *pvh, *poh, *pt, *pa, *pb;
    cudaGetSymbolAddress((void**)&pv,  g_v);
    cudaGetSymbolAddress((void**)&pvh, g_vhull);
    cudaGetSymbolAddress((void**)&poh, g_oh);
    cudaGetSymbolAddress((void**)&pt,  g_t128);
    cudaGetSymbolAddress((void**)&pa,  g_a256);
    cudaGetSymbolAddress((void**)&pb,  g_b256);

    cudaFuncSetAttribute(hull_kernel, cudaFuncAttributeMaxDynamicSharedMemorySize,
                         (int)(HULL_SMEM_FLOATS * sizeof(float)));

    // 1. zero accumulators
    zero_kernel<<<2048, 256>>>(pv, poh, (size_t)N * 128);

    // 2. v = segment_sum(e2, i)
    {
        long long threads = (long long)E * 32;
        int blocks = (int)((threads + 255) / 256);
        scatter_kernel<<<blocks, 256>>>((const float4*)e2, iedge, pv, E);
    }

    // 3. v_hull = v @ w_hull
    launch_gemm(pv, 128, 128, pv, 128, w_hull, nullptr, pvh, N, 128, 128, 0);

    // 4. hull message passing
    hull_kernel<<<296, 256, HULL_SMEM_FLOATS * sizeof(float)>>>(
        fea, jh, ih, w0, b0, w1, b1, pvh, poh, EH);

    // 5. t128 = silu(oh @ w1_hull + b1_hull)
    launch_gemm(poh, 128, 128, poh, 128, w1h, b1h, pt, N, 128, 128, 1);
    // 6. a256 = t128 @ w2_hull + b2_hull
    launch_gemm(pt, 128, 128, pt, 128, w2h, b2h, pa, N, 128, 256, 0);
    // 7. t128 = silu([v | a256] @ w_cat + b_cat)
    launch_gemm(pv, 128, 128, pa, 256, wcat, bcat, pt, N, 384, 128, 1);
    // 8. b256 = t128 @ w_up + b_up
    launch_gemm(pt, 128, 128, pt, 128, wup, bup, pb, N, 128, 256, 0);
    // 9. a256 = silu(b256 @ w_l0 + b_l0)
    launch_gemm(pb, 256, 256, pb, 256, wl0, bl0, pa, N, 256, 256, 1);
    // 10. b256 = silu(a256 @ w_l1 + b_l1)
    launch_gemm(pa, 256, 256, pa, 256, wl1, bl1, pb, N, 256, 256, 1);
    // 11. out = b256 @ w_out
    {
        int blocks = (N + 7) / 8;
        out_kernel<<<blocks, 256>>>(pb, wout, out, N);
    }
}

// round 5
// speedup vs baseline: 2.8922x; 1.3185x over previous
#include <cuda_runtime.h>
#include <cuda_bf16.h>
#include <math.h>
#include <stdint.h>

#define NMAX 100000
#define KBLK 32      // K elements per SMEM tile block (node GEMM)
#define HTILE 32     // hull edges per tile
#define SAS 40       // node GEMM sA stride in bf16
#define SBS 42       // node GEMM sB stride in bf16
#define HSAS 136     // hull hid stride in bf16
#define HSBS 136     // hull w1 stride in bf16

// ---------------- scratch ----------------
__device__ float g_v   [(size_t)NMAX * 128];
__device__ float g_vhull[(size_t)NMAX * 128];
__device__ float g_oh  [(size_t)NMAX * 128];
__device__ float g_t128[(size_t)NMAX * 128];
__device__ float g_a256[(size_t)NMAX * 256];
__device__ float g_b256[(size_t)NMAX * 256];

__device__ __forceinline__ float silu_f(float x) { return x / (1.0f + expf(-x)); }

__device__ __forceinline__ void mma_bf16(float* c, uint32_t a0, uint32_t a1,
                                         uint32_t a2, uint32_t a3,
                                         uint32_t b0, uint32_t b1) {
    asm volatile(
        "mma.sync.aligned.m16n8k16.row.col.f32.bf16.bf16.f32 "
        "{%0,%1,%2,%3}, {%4,%5,%6,%7}, {%8,%9}, {%0,%1,%2,%3};"
        : "+f"(c[0]), "+f"(c[1]), "+f"(c[2]), "+f"(c[3])
        : "r"(a0), "r"(a1), "r"(a2), "r"(a3), "r"(b0), "r"(b1));
}

__device__ __forceinline__ uint32_t packbf(__nv_bfloat16 lo, __nv_bfloat16 hi) {
    return (uint32_t)__bfloat16_as_ushort(lo) | ((uint32_t)__bfloat16_as_ushort(hi) << 16);
}

// ---------------- simple kernels ----------------
__global__ void zero_kernel(float* a, float* b, size_t n)
{
    size_t t = (size_t)blockIdx.x * blockDim.x + threadIdx.x;
    size_t stride = (size_t)gridDim.x * blockDim.x;
    for (size_t x = t; x < n; x += stride) { a[x] = 0.0f; b[x] = 0.0f; }
}

__global__ void scatter_kernel(const float4* __restrict__ e2,
                               const int* __restrict__ idx,
                               float* __restrict__ v, int E)
{
    int t = blockIdx.x * blockDim.x + threadIdx.x;
    int e = t >> 5;
    int c = t & 31;
    if (e >= E) return;
    float4 val = e2[(size_t)e * 32 + c];
    int node = idx[e];
    float* dst = v + (size_t)node * 128 + c * 4;
    atomicAdd(dst + 0, val.x);
    atomicAdd(dst + 1, val.y);
    atomicAdd(dst + 2, val.z);
    atomicAdd(dst + 3, val.w);
}

__global__ void out_kernel(const float* __restrict__ A,
                           const float* __restrict__ w,
                           float* __restrict__ out, int Nrows)
{
    int gwarp = (blockIdx.x * blockDim.x + threadIdx.x) >> 5;
    int lane = threadIdx.x & 31;
    if (gwarp >= Nrows) return;
    const float* row = A + (size_t)gwarp * 256;
    float acc = 0.0f;
#pragma unroll
    for (int k = lane; k < 256; k += 32) acc += row[k] * __ldg(&w[k]);
#pragma unroll
    for (int o = 16; o > 0; o >>= 1) acc += __shfl_down_sync(0xffffffff, acc, o);
    if (lane == 0) out[gwarp] = acc;
}

// ---------------- warp-MMA bf16 split-3 GEMM (node chain) ----------------
__global__ __launch_bounds__(256, 2) void gemm_mma(
    const float* __restrict__ A0, int lda0, int ksplit,
    const float* __restrict__ A1, int lda1,
    const float* __restrict__ W, const float* __restrict__ bias,
    float* __restrict__ C, int Nrows, int K, int M, int act)
{
    __shared__ __nv_bfloat16 sAhi[128 * SAS];
    __shared__ __nv_bfloat16 sAlo[128 * SAS];
    __shared__ __nv_bfloat16 sBhi[128 * SBS];
    __shared__ __nv_bfloat16 sBlo[128 * SBS];

    int tid = threadIdx.x;
    int wid = tid >> 5;
    int lane = tid & 31;
    int warpRow = wid & 3;
    int warpCol = wid >> 2;
    int row0 = blockIdx.x * 128;
    int col0 = blockIdx.y * 128;

    float c[2][8][4];
#pragma unroll
    for (int mf = 0; mf < 2; mf++)
#pragma unroll
        for (int nf = 0; nf < 8; nf++)
#pragma unroll
            for (int q = 0; q < 4; q++) c[mf][nf][q] = 0.0f;

    int qrow = lane >> 2;
    int qcol = lane & 3;

    for (int k0 = 0; k0 < K; k0 += KBLK) {
        const float* srcA;
        int kbase, ld;
        if (k0 < ksplit) { srcA = A0; kbase = k0; ld = lda0; }
        else             { srcA = A1; kbase = k0 - ksplit; ld = lda1; }
#pragma unroll
        for (int it = 0; it < 4; it++) {
            int idx = tid + it * 256;
            int r = idx >> 3;
            int kq = (idx & 7) * 4;
            float4 v = make_float4(0.f, 0.f, 0.f, 0.f);
            int grow = row0 + r;
            if (grow < Nrows)
                v = *(const float4*)&srcA[(size_t)grow * ld + kbase + kq];
            __nv_bfloat16 h0 = __float2bfloat16(v.x), h1 = __float2bfloat16(v.y);
            __nv_bfloat16 h2 = __float2bfloat16(v.z), h3 = __float2bfloat16(v.w);
            __nv_bfloat16 l0 = __float2bfloat16(v.x - __bfloat162float(h0));
            __nv_bfloat16 l1 = __float2bfloat16(v.y - __bfloat162float(h1));
            __nv_bfloat16 l2 = __float2bfloat16(v.z - __bfloat162float(h2));
            __nv_bfloat16 l3 = __float2bfloat16(v.w - __bfloat162float(h3));
            int base = r * SAS + kq;
            *(uint32_t*)&sAhi[base]     = packbf(h0, h1);
            *(uint32_t*)&sAhi[base + 2] = packbf(h2, h3);
            *(uint32_t*)&sAlo[base]     = packbf(l0, l1);
            *(uint32_t*)&sAlo[base + 2] = packbf(l2, l3);
        }
#pragma unroll
        for (int it = 0; it < 4; it++) {
            int idx = tid + it * 256;
            int k = idx >> 5;
            int nq = (idx & 31) * 4;
            float4 v = *(const float4*)&W[(size_t)(k0 + k) * M + col0 + nq];
            __nv_bfloat16 h0 = __float2bfloat16(v.x), h1 = __float2bfloat16(v.y);
            __nv_bfloat16 h2 = __float2bfloat16(v.z), h3 = __float2bfloat16(v.w);
            __nv_bfloat16 l0 = __float2bfloat16(v.x - __bfloat162float(h0));
            __nv_bfloat16 l1 = __float2bfloat16(v.y - __bfloat162float(h1));
            __nv_bfloat16 l2 = __float2bfloat16(v.z - __bfloat162float(h2));
            __nv_bfloat16 l3 = __float2bfloat16(v.w - __bfloat162float(h3));
            sBhi[(nq + 0) * SBS + k] = h0;  sBlo[(nq + 0) * SBS + k] = l0;
            sBhi[(nq + 1) * SBS + k] = h1;  sBlo[(nq + 1) * SBS + k] = l1;
            sBhi[(nq + 2) * SBS + k] = h2;  sBlo[(nq + 2) * SBS + k] = l2;
            sBhi[(nq + 3) * SBS + k] = h3;  sBlo[(nq + 3) * SBS + k] = l3;
        }
        __syncthreads();

#pragma unroll
        for (int kc = 0; kc < KBLK; kc += 16) {
            uint32_t ah[2][4], al[2][4];
#pragma unroll
            for (int mf = 0; mf < 2; mf++) {
                int r = warpRow * 32 + mf * 16 + qrow;
                int i0 = r * SAS + kc + 2 * qcol;
                ah[mf][0] = *(const uint32_t*)&sAhi[i0];
                ah[mf][1] = *(const uint32_t*)&sAhi[i0 + 8 * SAS];
                ah[mf][2] = *(const uint32_t*)&sAhi[i0 + 8];
                ah[mf][3] = *(const uint32_t*)&sAhi[i0 + 8 * SAS + 8];
                al[mf][0] = *(const uint32_t*)&sAlo[i0];
                al[mf][1] = *(const uint32_t*)&sAlo[i0 + 8 * SAS];
                al[mf][2] = *(const uint32_t*)&sAlo[i0 + 8];
                al[mf][3] = *(const uint32_t*)&sAlo[i0 + 8 * SAS + 8];
            }
#pragma unroll
            for (int nf = 0; nf < 8; nf++) {
                int n = warpCol * 64 + nf * 8 + qrow;
                int i0 = n * SBS + kc + 2 * qcol;
                uint32_t bh0 = *(const uint32_t*)&sBhi[i0];
                uint32_t bh1 = *(const uint32_t*)&sBhi[i0 + 8];
                uint32_t bl0 = *(const uint32_t*)&sBlo[i0];
                uint32_t bl1 = *(const uint32_t*)&sBlo[i0 + 8];
#pragma unroll
                for (int mf = 0; mf < 2; mf++) {
                    mma_bf16(c[mf][nf], ah[mf][0], ah[mf][1], ah[mf][2], ah[mf][3], bh0, bh1);
                    mma_bf16(c[mf][nf], ah[mf][0], ah[mf][1], ah[mf][2], ah[mf][3], bl0, bl1);
                    mma_bf16(c[mf][nf], al[mf][0], al[mf][1], al[mf][2], al[mf][3], bh0, bh1);
                }
            }
        }
        __syncthreads();
    }

#pragma unroll
    for (int mf = 0; mf < 2; mf++) {
        int rbase = row0 + warpRow * 32 + mf * 16 + qrow;
#pragma unroll
        for (int nf = 0; nf < 8; nf++) {
            int colp = col0 + warpCol * 64 + nf * 8 + 2 * qcol;
            float b0v = 0.f, b1v = 0.f;
            if (bias) { b0v = bias[colp]; b1v = bias[colp + 1]; }
            float f0 = c[mf][nf][0] + b0v;
            float f1 = c[mf][nf][1] + b1v;
            float f2 = c[mf][nf][2] + b0v;
            float f3 = c[mf][nf][3] + b1v;
            if (act) { f0 = silu_f(f0); f1 = silu_f(f1); f2 = silu_f(f2); f3 = silu_f(f3); }
            if (rbase < Nrows)
                *(float2*)&C[(size_t)rbase * M + colp] = make_float2(f0, f1);
            if (rbase + 8 < Nrows)
                *(float2*)&C[(size_t)(rbase + 8) * M + colp] = make_float2(f2, f3);
        }
    }
}

// ---------------- hull kernel: MLP + MMA + gather/scatter ----------------
// Per 32-edge tile: hid = silu(fea@w0+b0) [32,128] (scalar, K=16);
// Wh = hid @ w1 + b1 via split-3 bf16 MMA (M=32,N=128,K=128);
// oh[i] += vhull[j] * Wh (atomic).
#define HULL_SMEM_BYTES ((2 * 128 * HSBS + 2 * HTILE * HSAS) * 2 + (HTILE * 16 + 128) * 4)

__global__ __launch_bounds__(256, 2) void hull_kernel(
    const float* __restrict__ fea,
    const int* __restrict__ jidx, const int* __restrict__ iidx,
    const float* __restrict__ w0, const float* __restrict__ b0,
    const float* __restrict__ w1, const float* __restrict__ b1,
    const float* __restrict__ vhull, float* __restrict__ oh, int EHn)
{
    extern __shared__ char smraw[];
    __nv_bfloat16* s_w1hi  = (__nv_bfloat16*)smraw;            // 128*HSBS
    __nv_bfloat16* s_w1lo  = s_w1hi + 128 * HSBS;
    __nv_bfloat16* s_hidhi = s_w1lo + 128 * HSBS;              // HTILE*HSAS
    __nv_bfloat16* s_hidlo = s_hidhi + HTILE * HSAS;
    float* s_fea = (float*)(s_hidlo + HTILE * HSAS);           // HTILE*16
    float* s_b1  = s_fea + HTILE * 16;                         // 128

    int tid = threadIdx.x;
    int wid = tid >> 5;
    int lane = tid & 31;
    int warpRow = wid & 1;        // 2 x 16 rows
    int warpCol = wid >> 1;       // 4 x 32 cols
    int qrow = lane >> 2;
    int qcol = lane & 3;
    int col = tid & 127;
    int wg  = tid >> 7;

    // one-time: w1 -> split bf16, B-layout [n][k]
    for (int t = tid; t < 16384; t += 256) {
        int k = t >> 7, n = t & 127;
        float v = w1[t];
        __nv_bfloat16 h = __float2bfloat16(v);
        __nv_bfloat16 l = __float2bfloat16(v - __bfloat162float(h));
        s_w1hi[n * HSBS + k] = h;
        s_w1lo[n * HSBS + k] = l;
    }
    if (tid < 128) s_b1[tid] = b1[tid];
    float rw0[16];
#pragma unroll
    for (int k = 0; k < 16; k++) rw0[k] = w0[k * 128 + col];
    float rb0 = b0[col];
    __syncthreads();

    for (int base = blockIdx.x * HTILE; base < EHn; base += gridDim.x * HTILE) {
        int ec = min(HTILE, EHn - base);

        for (int t = tid; t < ec * 16; t += 256)
            s_fea[t] = fea[(size_t)base * 16 + t];
        __syncthreads();

        // hidden: wg g handles edges [g*16, g*16+16); thread owns column `col`
        int e0 = wg * 16, e1 = min(ec, e0 + 16);
        for (int e = e0; e < e1; e++) {
            float acc = rb0;
#pragma unroll
            for (int k = 0; k < 16; k++)
                acc += s_fea[e * 16 + k] * rw0[k];
            float hv = silu_f(acc);
            __nv_bfloat16 h = __float2bfloat16(hv);
            __nv_bfloat16 l = __float2bfloat16(hv - __bfloat162float(h));
            s_hidhi[e * HSAS + col] = h;
            s_hidlo[e * HSAS + col] = l;
        }
        __syncthreads();

        // MMA: Wh[32,128] = hid @ w1  (split-3)
        float c[4][4];
#pragma unroll
        for (int nf = 0; nf < 4; nf++)
#pragma unroll
            for (int q = 0; q < 4; q++) c[nf][q] = 0.0f;

#pragma unroll
        for (int kc = 0; kc < 128; kc += 16) {
            int i0 = (warpRow * 16 + qrow) * HSAS + kc + 2 * qcol;
            uint32_t ah0 = *(const uint32_t*)&s_hidhi[i0];
            uint32_t ah1 = *(const uint32_t*)&s_hidhi[i0 + 8 * HSAS];
            uint32_t ah2 = *(const uint32_t*)&s_hidhi[i0 + 8];
            uint32_t ah3 = *(const uint32_t*)&s_hidhi[i0 + 8 * HSAS + 8];
            uint32_t al0 = *(const uint32_t*)&s_hidlo[i0];
            uint32_t al1 = *(const uint32_t*)&s_hidlo[i0 + 8 * HSAS];
            uint32_t al2 = *(const uint32_t*)&s_hidlo[i0 + 8];
            uint32_t al3 = *(const uint32_t*)&s_hidlo[i0 + 8 * HSAS + 8];
#pragma unroll
            for (int nf = 0; nf < 4; nf++) {
                int n = warpCol * 32 + nf * 8 + qrow;
                int j0 = n * HSBS + kc + 2 * qcol;
                uint32_t bh0 = *(const uint32_t*)&s_w1hi[j0];
                uint32_t bh1 = *(const uint32_t*)&s_w1hi[j0 + 8];
                uint32_t bl0 = *(const uint32_t*)&s_w1lo[j0];
                uint32_t bl1 = *(const uint32_t*)&s_w1lo[j0 + 8];
                mma_bf16(c[nf], ah0, ah1, ah2, ah3, bh0, bh1);
                mma_bf16(c[nf], ah0, ah1, ah2, ah3, bl0, bl1);
                mma_bf16(c[nf], al0, al1, al2, al3, bh0, bh1);
            }
        }

        // epilogue: per-fragment gather-multiply-scatter
        int eA = warpRow * 16 + qrow;
        int eB = eA + 8;
        int jA = 0, iA = 0, jB = 0, iB = 0;
        bool vA = eA < ec, vB = eB < ec;
        if (vA) { jA = jidx[base + eA]; iA = iidx[base + eA]; }
        if (vB) { jB = jidx[base + eB]; iB = iidx[base + eB]; }
#pragma unroll
        for (int nf = 0; nf < 4; nf++) {
            int cp = warpCol * 32 + nf * 8 + 2 * qcol;
            float bb0 = s_b1[cp], bb1 = s_b1[cp + 1];
            if (vA) {
                float2 vh = *(const float2*)&vhull[(size_t)jA * 128 + cp];
                float f0 = (c[nf][0] + bb0) * vh.x;
                float f1 = (c[nf][1] + bb1) * vh.y;
                atomicAdd(&oh[(size_t)iA * 128 + cp], f0);
                atomicAdd(&oh[(size_t)iA * 128 + cp + 1], f1);
            }
            if (vB) {
                float2 vh = *(const float2*)&vhull[(size_t)jB * 128 + cp];
                float f2 = (c[nf][2] + bb0) * vh.x;
                float f3 = (c[nf][3] + bb1) * vh.y;
                atomicAdd(&oh[(size_t)iB * 128 + cp], f2);
                atomicAdd(&oh[(size_t)iB * 128 + cp + 1], f3);
            }
        }
        __syncthreads();
    }
}

// ---------------- launch ----------------
static void launch_gemm(const float* A0, int lda0, int ksplit,
                        const float* A1, int lda1,
                        const float* W, const float* bias,
                        float* C, int N, int K, int M, int act)
{
    dim3 grid((N + 127) / 128, M / 128);
    gemm_mma<<<grid, 256>>>(A0, lda0, ksplit, A1, lda1, W, bias, C, N, K, M, act);
}

extern "C" void kernel_launch(void* const* d_in, const int* in_sizes, int n_in,
                              void* d_out, int out_size)
{
    const float* e2    = (const float*)d_in[0];
    const int*   iedge = (const int*)  d_in[1];
    const float* fea   = (const float*)d_in[2];
    const int*   eih   = (const int*)  d_in[3];
    const float* w_hull= (const float*)d_in[4];
    const float* w0    = (const float*)d_in[5];
    const float* b0    = (const float*)d_in[6];
    const float* w1    = (const float*)d_in[7];
    const float* b1    = (const float*)d_in[8];
    const float* w1h   = (const float*)d_in[9];
    const float* b1h   = (const float*)d_in[10];
    const float* w2h   = (const float*)d_in[11];
    const float* b2h   = (const float*)d_in[12];
    const float* wcat  = (const float*)d_in[13];
    const float* bcat  = (const float*)d_in[14];
    const float* wup   = (const float*)d_in[15];
    const float* bup   = (const float*)d_in[16];
    const float* wl0   = (const float*)d_in[17];
    const float* bl0   = (const float*)d_in[18];
    const float* wl1   = (const float*)d_in[19];
    const float* bl1   = (const float*)d_in[20];
    const float* wout  = (const float*)d_in[21];
    float* out = (float*)d_out;

    int N  = out_size;
    int E  = in_sizes[1];
    int EH = in_sizes[2] / 16;
    const int* jh = eih;
    const int* ih = eih + EH;

    float *pv, *pvh, *poh, *pt, *pa, *pb;
    cudaGetSymbolAddress((void**)&pv,  g_v);
    cudaGetSymbolAddress((void**)&pvh, g_vhull);
    cudaGetSymbolAddress((void**)&poh, g_oh);
    cudaGetSymbolAddress((void**)&pt,  g_t128);
    cudaGetSymbolAddress((void**)&pa,  g_a256);
    cudaGetSymbolAddress((void**)&pb,  g_b256);

    cudaFuncSetAttribute(hull_kernel, cudaFuncAttributeMaxDynamicSharedMemorySize,
                         HULL_SMEM_BYTES);
    cudaFuncSetAttribute(hull_kernel, cudaFuncAttributePreferredSharedMemoryCarveout,
                         100);

    // 1. zero accumulators
    zero_kernel<<<2048, 256>>>(pv, poh, (size_t)N * 128);

    // 2. v = segment_sum(e2, i)
    {
        long long threads = (long long)E * 32;
        int blocks = (int)((threads + 255) / 256);
        scatter_kernel<<<blocks, 256>>>((const float4*)e2, iedge, pv, E);
    }

    // 3. v_hull = v @ w_hull
    launch_gemm(pv, 128, 128, pv, 128, w_hull, nullptr, pvh, N, 128, 128, 0);

    // 4. hull message passing (MMA)
    hull_kernel<<<296, 256, HULL_SMEM_BYTES>>>(
        fea, jh, ih, w0, b0, w1, b1, pvh, poh, EH);

    // 5. t128 = silu(oh @ w1_hull + b1_hull)
    launch_gemm(poh, 128, 128, poh, 128, w1h, b1h, pt, N, 128, 128, 1);
    // 6. a256 = t128 @ w2_hull + b2_hull
    launch_gemm(pt, 128, 128, pt, 128, w2h, b2h, pa, N, 128, 256, 0);
    // 7. t128 = silu([v | a256] @ w_cat + b_cat)
    launch_gemm(pv, 128, 128, pa, 256, wcat, bcat, pt, N, 384, 128, 1);
    // 8. b256 = t128 @ w_up + b_up
    launch_gemm(pt, 128, 128, pt, 128, wup, bup, pb, N, 128, 256, 0);
    // 9. a256 = silu(b256 @ w_l0 + b_l0)
    launch_gemm(pb, 256, 256, pb, 256, wl0, bl0, pa, N, 256, 256, 1);
    // 10. b256 = silu(a256 @ w_l1 + b_l1)
    launch_gemm(pa, 256, 256, pa, 256, wl1, bl1, pb, N, 256, 256, 1);
    // 11. out = b256 @ w_out
    {
        int blocks = (N + 7) / 8;
        out_kernel<<<blocks, 256>>>(pb, wout, out, N);
    }
}